// round 5
// baseline (speedup 1.0000x reference)
#include <cuda_runtime.h>
#include <cstdint>

#define MULC 32
#define IN_DIM 128
#define W_DIM 160
#define OUT_DIM 224

__device__ __forceinline__ void red_add_v4(float* addr, float a, float b, float c, float d) {
    asm volatile("red.global.add.v4.f32 [%0], {%1, %2, %3, %4};"
                 :: "l"(addr), "f"(a), "f"(b), "f"(c), "f"(d)
                 : "memory");
}

__global__ void zero_out_kernel(float4* __restrict__ out, int n4) {
    int i = blockIdx.x * blockDim.x + threadIdx.x;
    if (i < n4) out[i] = make_float4(0.f, 0.f, 0.f, 0.f);
}

__global__ __launch_bounds__(256) void conv_tp_kernel(
    const float* __restrict__ nf,        // [n_nodes, 128]
    const float4* __restrict__ ang,      // [n_edges, 4] viewed as float4
    const int2* __restrict__ eidx,       // [n_edges, 2] int32
    const float* __restrict__ tp,        // [n_edges, 160]
    float* __restrict__ out,             // [n_nodes, 224]
    int n_edges)
{
    const float INV_SQRT3 = 0.5773502691896258f;
    const float INV_SQRT2 = 0.7071067811865476f;

    int tid = blockIdx.x * 256 + threadIdx.x;
    int e = tid >> 3;      // edge index
    int g = tid & 7;       // channel group: channels 4g..4g+3
    if (e >= n_edges) return;

    int2 se = eidx[e];
    int src = se.x;
    int dst = se.y;

    float4 y = ang[e];     // broadcast among the 8 lanes of this edge
    float y0 = y.x, yx = y.y, yy = y.z, yz = y.w;

    const float4* hb = (const float4*)(nf + (size_t)src * IN_DIM);
    float4 h0v  = hb[g];
    float4 h1xv = hb[8 + g];
    float4 h1yv = hb[16 + g];
    float4 h1zv = hb[24 + g];

    const float4* wb = (const float4*)(tp + (size_t)e * W_DIM);
    float4 w0v = wb[g];
    float4 w1v = wb[8 + g];
    float4 w2v = wb[16 + g];
    float4 w3v = wb[24 + g];
    float4 w4v = wb[32 + g];

    const float* h0p  = (const float*)&h0v;
    const float* h1xp = (const float*)&h1xv;
    const float* h1yp = (const float*)&h1yv;
    const float* h1zp = (const float*)&h1zv;
    const float* w0p  = (const float*)&w0v;
    const float* w1p  = (const float*)&w1v;
    const float* w2p  = (const float*)&w2v;
    const float* w3p  = (const float*)&w3v;
    const float* w4p  = (const float*)&w4v;

    float o0[4];
    float o1[3][4];
    float oe[3][4];

    #pragma unroll
    for (int i = 0; i < 4; i++) {
        float H0 = h0p[i], Hx = h1xp[i], Hy = h1yp[i], Hz = h1zp[i];
        float W0 = w0p[i], W1 = w1p[i], W2 = w2p[i], W3 = w3p[i], W4 = w4p[i];

        float dot = Hx * yx + Hy * yy + Hz * yz;
        o0[i] = W0 * (H0 * y0) + (W3 * INV_SQRT3) * dot;

        float a = W1 * H0;
        float b = W2 * y0;
        o1[0][i] = a * yx + b * Hx;
        o1[1][i] = a * yy + b * Hy;
        o1[2][i] = a * yz + b * Hz;

        float s = W4 * INV_SQRT2;
        oe[0][i] = s * (Hy * yz - Hz * yy);
        oe[1][i] = s * (Hz * yx - Hx * yz);
        oe[2][i] = s * (Hx * yy - Hy * yx);
    }

    float* ob = out + (size_t)dst * OUT_DIM + 4 * g;
    // layout: [out0e(32) | out1o(3*32) | out1e(3*32)]
    red_add_v4(ob,              o0[0],    o0[1],    o0[2],    o0[3]);
    red_add_v4(ob + 32,         o1[0][0], o1[0][1], o1[0][2], o1[0][3]);
    red_add_v4(ob + 64,         o1[1][0], o1[1][1], o1[1][2], o1[1][3]);
    red_add_v4(ob + 96,         o1[2][0], o1[2][1], o1[2][2], o1[2][3]);
    red_add_v4(ob + 128,        oe[0][0], oe[0][1], oe[0][2], oe[0][3]);
    red_add_v4(ob + 160,        oe[1][0], oe[1][1], oe[1][2], oe[1][3]);
    red_add_v4(ob + 192,        oe[2][0], oe[2][1], oe[2][2], oe[2][3]);
}

extern "C" void kernel_launch(void* const* d_in, const int* in_sizes, int n_in,
                              void* d_out, int out_size) {
    const float*  nf   = (const float*)d_in[0];      // node_features [n,128]
    const float4* ang  = (const float4*)d_in[1];     // edge_angular  [E,4]
    const int2*   eidx = (const int2*)d_in[2];       // edge_index    [E,2] int32
    const float*  tp   = (const float*)d_in[3];      // tp_weights    [E,160]
    float*        out  = (float*)d_out;

    int n_edges = in_sizes[1] / 4;

    // zero the output (atomics accumulate; d_out is poisoned before timing)
    int n4 = out_size / 4;
    zero_out_kernel<<<(n4 + 255) / 256, 256>>>((float4*)d_out, n4);

    int total_threads = n_edges * 8;
    int blocks = (total_threads + 255) / 256;
    conv_tp_kernel<<<blocks, 256>>>(nf, ang, eidx, tp, out, n_edges);
}

// round 6
// speedup vs baseline: 1.1202x; 1.1202x over previous
#include <cuda_runtime.h>
#include <cstdint>

#define MULC 32
#define IN_DIM 128
#define W_DIM 160
#define OUT_DIM 224

__device__ __forceinline__ void red_add_v4(float* addr, float a, float b, float c, float d) {
    asm volatile("red.global.add.v4.f32 [%0], {%1, %2, %3, %4};"
                 :: "l"(addr), "f"(a), "f"(b), "f"(c), "f"(d)
                 : "memory");
}

__global__ void zero_out_kernel(float4* __restrict__ out, int n4) {
    int i = blockIdx.x * blockDim.x + threadIdx.x;
    if (i < n4) out[i] = make_float4(0.f, 0.f, 0.f, 0.f);
}

__global__ __launch_bounds__(256) void conv_tp_kernel(
    const float* __restrict__ nf,        // [n_nodes, 128]
    const float4* __restrict__ ang,      // [n_edges, 4] viewed as float4
    const int2* __restrict__ eidx,       // [n_edges, 2] int32
    const float* __restrict__ tp,        // [n_edges, 160]
    float* __restrict__ out,             // [n_nodes, 224]
    int n_edges)
{
    const float INV_SQRT3 = 0.5773502691896258f;
    const float INV_SQRT2 = 0.7071067811865476f;

    int tid = blockIdx.x * 256 + threadIdx.x;
    int e = tid >> 3;      // edge index
    int g = tid & 7;       // channel group: channels 4g..4g+3
    if (e >= n_edges) return;

    // Stream-once data: evict-first so it doesn't pollute L2
    // (node table + output atomics need to stay L2-resident).
    int2 se = __ldcs(&eidx[e]);
    int src = se.x;
    int dst = se.y;

    float4 y = __ldcs(&ang[e]);
    float y0 = y.x, yx = y.y, yy = y.z, yz = y.w;

    // Node-feature gather: default caching (small table, heavy reuse)
    const float4* hb = (const float4*)(nf + (size_t)src * IN_DIM);
    float4 h0v  = __ldg(&hb[g]);
    float4 h1xv = __ldg(&hb[8 + g]);
    float4 h1yv = __ldg(&hb[16 + g]);
    float4 h1zv = __ldg(&hb[24 + g]);

    const float4* wb = (const float4*)(tp + (size_t)e * W_DIM);
    float4 w0v = __ldcs(&wb[g]);
    float4 w1v = __ldcs(&wb[8 + g]);
    float4 w2v = __ldcs(&wb[16 + g]);
    float4 w3v = __ldcs(&wb[24 + g]);
    float4 w4v = __ldcs(&wb[32 + g]);

    const float* h0p  = (const float*)&h0v;
    const float* h1xp = (const float*)&h1xv;
    const float* h1yp = (const float*)&h1yv;
    const float* h1zp = (const float*)&h1zv;
    const float* w0p  = (const float*)&w0v;
    const float* w1p  = (const float*)&w1v;
    const float* w2p  = (const float*)&w2v;
    const float* w3p  = (const float*)&w3v;
    const float* w4p  = (const float*)&w4v;

    float o0[4];
    float o1[3][4];
    float oe[3][4];

    #pragma unroll
    for (int i = 0; i < 4; i++) {
        float H0 = h0p[i], Hx = h1xp[i], Hy = h1yp[i], Hz = h1zp[i];
        float W0 = w0p[i], W1 = w1p[i], W2 = w2p[i], W3 = w3p[i], W4 = w4p[i];

        float dot = Hx * yx + Hy * yy + Hz * yz;
        o0[i] = W0 * (H0 * y0) + (W3 * INV_SQRT3) * dot;

        float a = W1 * H0;
        float b = W2 * y0;
        o1[0][i] = a * yx + b * Hx;
        o1[1][i] = a * yy + b * Hy;
        o1[2][i] = a * yz + b * Hz;

        float s = W4 * INV_SQRT2;
        oe[0][i] = s * (Hy * yz - Hz * yy);
        oe[1][i] = s * (Hz * yx - Hx * yz);
        oe[2][i] = s * (Hx * yy - Hy * yx);
    }

    float* ob = out + (size_t)dst * OUT_DIM + 4 * g;
    // layout: [out0e(32) | out1o(3*32) | out1e(3*32)]
    red_add_v4(ob,              o0[0],    o0[1],    o0[2],    o0[3]);
    red_add_v4(ob + 32,         o1[0][0], o1[0][1], o1[0][2], o1[0][3]);
    red_add_v4(ob + 64,         o1[1][0], o1[1][1], o1[1][2], o1[1][3]);
    red_add_v4(ob + 96,         o1[2][0], o1[2][1], o1[2][2], o1[2][3]);
    red_add_v4(ob + 128,        oe[0][0], oe[0][1], oe[0][2], oe[0][3]);
    red_add_v4(ob + 160,        oe[1][0], oe[1][1], oe[1][2], oe[1][3]);
    red_add_v4(ob + 192,        oe[2][0], oe[2][1], oe[2][2], oe[2][3]);
}

extern "C" void kernel_launch(void* const* d_in, const int* in_sizes, int n_in,
                              void* d_out, int out_size) {
    const float*  nf   = (const float*)d_in[0];      // node_features [n,128]
    const float4* ang  = (const float4*)d_in[1];     // edge_angular  [E,4]
    const int2*   eidx = (const int2*)d_in[2];       // edge_index    [E,2] int32
    const float*  tp   = (const float*)d_in[3];      // tp_weights    [E,160]
    float*        out  = (float*)d_out;

    int n_edges = in_sizes[1] / 4;

    // zero the output (atomics accumulate; d_out is poisoned before timing)
    int n4 = out_size / 4;
    zero_out_kernel<<<(n4 + 255) / 256, 256>>>((float4*)d_out, n4);

    int total_threads = n_edges * 8;
    int blocks = (total_threads + 255) / 256;
    conv_tp_kernel<<<blocks, 256>>>(nf, ang, eidx, tp, out, n_edges);
}